// round 1
// baseline (speedup 1.0000x reference)
#include <cuda_runtime.h>

// ChamferLoss: B=4, N=M=8192, 3D points.
// dist(i,j) = |p_i|^2 + |q_j|^2 - 2 p_i.q_j
// Shared tile holds (-2x, -2y, -2z, |q|^2) per j point -> 3 FFMA + 1 FMNMX per pair.

#define BB 4
#define NPTS 8192
#define MPTS 8192

__device__ float g_d1[BB * NPTS];
__device__ float g_d2[BB * MPTS];

__global__ void chamfer_init_kernel() {
    int idx = blockIdx.x * blockDim.x + threadIdx.x;
    if (idx < BB * NPTS) ((int*)g_d1)[idx] = 0x7f800000;  // +inf
    if (idx < BB * MPTS) ((int*)g_d2)[idx] = 0x7f800000;
}

// DIR = 0: A = xyz1 (write g_d1), DIR = 1: A = xyz2 (write g_d2)
// Each thread owns IPT points of A; block sweeps a jchunk of B-points via smem tile.
template <int DIR, int IPT, int TJ>
__global__ void __launch_bounds__(256) chamfer_min_kernel(
    const float* __restrict__ Apts, const float* __restrict__ Bpts,
    int Na, int Nb, int jchunk)
{
    __shared__ float4 tile[TJ];
    const int b = blockIdx.z;
    const int iBase = blockIdx.x * (blockDim.x * IPT);
    const int jBase = blockIdx.y * jchunk;
    const float* __restrict__ Ab = Apts + (size_t)b * Na * 3;
    const float* __restrict__ Bb = Bpts + (size_t)b * Nb * 3;

    float ax[IPT], ay[IPT], az[IPT], mn[IPT];
#pragma unroll
    for (int k = 0; k < IPT; k++) {
        int i = iBase + threadIdx.x + k * 256;
        ax[k] = Ab[i * 3 + 0];
        ay[k] = Ab[i * 3 + 1];
        az[k] = Ab[i * 3 + 2];
        mn[k] = 3.4e38f;
    }

    for (int j0 = 0; j0 < jchunk; j0 += TJ) {
        __syncthreads();
        for (int jj = threadIdx.x; jj < TJ; jj += 256) {
            int j = jBase + j0 + jj;
            float x = Bb[j * 3 + 0];
            float y = Bb[j * 3 + 1];
            float z = Bb[j * 3 + 2];
            float n2 = fmaf(x, x, fmaf(y, y, z * z));
            tile[jj] = make_float4(-2.f * x, -2.f * y, -2.f * z, n2);
        }
        __syncthreads();

#pragma unroll 4
        for (int jj = 0; jj < TJ; jj++) {
            float4 bv = tile[jj];
#pragma unroll
            for (int k = 0; k < IPT; k++) {
                float t = fmaf(bv.x, ax[k], bv.w);
                t = fmaf(bv.y, ay[k], t);
                t = fmaf(bv.z, az[k], t);
                mn[k] = fminf(mn[k], t);
            }
        }
    }

    float* outmin = (DIR == 0) ? g_d1 : g_d2;
#pragma unroll
    for (int k = 0; k < IPT; k++) {
        int i = iBase + threadIdx.x + k * 256;
        float n1 = fmaf(ax[k], ax[k], fmaf(ay[k], ay[k], az[k] * az[k]));
        float d = fmaxf(mn[k] + n1, 0.f);   // clamp: true dist >= 0; keeps int-ordered atomicMin valid
        atomicMin((int*)&outmin[b * Na + i], __float_as_int(d));
    }
}

__global__ void chamfer_reduce_kernel(float* __restrict__ out) {
    __shared__ float sh[32];
    float s = 0.f;
    for (int idx = threadIdx.x; idx < BB * NPTS; idx += blockDim.x)
        s += g_d1[idx] * (1.f / (BB * NPTS));
    for (int idx = threadIdx.x; idx < BB * MPTS; idx += blockDim.x)
        s += g_d2[idx] * (1.f / (BB * MPTS));
#pragma unroll
    for (int o = 16; o > 0; o >>= 1) s += __shfl_down_sync(0xffffffffu, s, o);
    if ((threadIdx.x & 31) == 0) sh[threadIdx.x >> 5] = s;
    __syncthreads();
    if (threadIdx.x < 32) {
        float v = (threadIdx.x < (blockDim.x >> 5)) ? sh[threadIdx.x] : 0.f;
#pragma unroll
        for (int o = 16; o > 0; o >>= 1) v += __shfl_down_sync(0xffffffffu, v, o);
        if (threadIdx.x == 0) out[0] = v;
    }
}

extern "C" void kernel_launch(void* const* d_in, const int* in_sizes, int n_in,
                              void* d_out, int out_size) {
    const float* xyz1 = (const float*)d_in[0];
    const float* xyz2 = (const float*)d_in[1];
    float* out = (float*)d_out;

    // Reset per-point min buffers to +inf every launch (graph-replay safe).
    chamfer_init_kernel<<<(BB * NPTS + 255) / 256, 256>>>();

    constexpr int IPT = 4;     // points of A per thread
    constexpr int TJ = 512;    // smem tile of B points
    constexpr int JSPLIT = 16; // j-range splits per batch (for grid parallelism)

    // Direction 1: for each point of xyz1, min over xyz2 -> g_d1
    {
        dim3 grid(NPTS / (256 * IPT), JSPLIT, BB);
        chamfer_min_kernel<0, IPT, TJ><<<grid, 256>>>(xyz1, xyz2, NPTS, MPTS, MPTS / JSPLIT);
    }
    // Direction 2: for each point of xyz2, min over xyz1 -> g_d2
    {
        dim3 grid(MPTS / (256 * IPT), JSPLIT, BB);
        chamfer_min_kernel<1, IPT, TJ><<<grid, 256>>>(xyz2, xyz1, MPTS, NPTS, NPTS / JSPLIT);
    }

    chamfer_reduce_kernel<<<1, 1024>>>(out);
}

// round 2
// speedup vs baseline: 1.0026x; 1.0026x over previous
#include <cuda_runtime.h>

// ChamferLoss: B=4, N=M=8192, 3D points.
// dist(i,j) = |p_i|^2 + (|q_j|^2 - 2 p_i.q_j); rowmin uses packed fma.rn.f32x2
// (2 pairs per instruction) -> 1.5 fma-pipe ops/pair instead of 3.

#define BB 4
#define NPTS 8192
#define MPTS 8192
#define IPT 8          // points of A per thread (must be even)
#define TJ 512         // smem tile of B points
#define JSPLIT 16      // j-range splits per (dir,b)

__device__ float g_d1[BB * NPTS];
__device__ float g_d2[BB * MPTS];
__device__ float g_part[64];

#define PACK2(out, lo, hi) \
    asm("mov.b64 %0, {%1, %2};" : "=l"(out) : "f"(lo), "f"(hi))
#define UNPACK2(lo, hi, in) \
    asm("mov.b64 {%0, %1}, %2;" : "=f"(lo), "=f"(hi) : "l"(in))
#define FMA2(d, a, b, c) \
    asm("fma.rn.f32x2 %0, %1, %2, %3;" : "=l"(d) : "l"(a), "l"(b), "l"(c))

__global__ void chamfer_init_kernel() {
    int idx = blockIdx.x * blockDim.x + threadIdx.x;
    if (idx < BB * NPTS) ((int*)g_d1)[idx] = 0x7f800000;  // +inf
    if (idx < BB * MPTS) ((int*)g_d2)[idx] = 0x7f800000;
}

// blockIdx.z encodes (dir, b): dir = z / BB, b = z % BB.
// dir 0: A = xyz1 -> g_d1 ; dir 1: A = xyz2 -> g_d2
__global__ void __launch_bounds__(256) chamfer_min_kernel(
    const float* __restrict__ xyz1, const float* __restrict__ xyz2)
{
    __shared__ float4 tile[TJ];
    const int dir = blockIdx.z / BB;
    const int b = blockIdx.z % BB;
    const float* __restrict__ Ab = (dir == 0 ? xyz1 : xyz2) + (size_t)b * NPTS * 3;
    const float* __restrict__ Bb = (dir == 0 ? xyz2 : xyz1) + (size_t)b * MPTS * 3;
    float* __restrict__ outmin = (dir == 0 ? g_d1 : g_d2) + b * NPTS;

    const int iBase = blockIdx.x * (256 * IPT);
    const int jBase = blockIdx.y * (MPTS / JSPLIT);

    // Load this thread's IPT A-points; pack coord pairs into f32x2 carriers.
    unsigned long long ax2[IPT / 2], ay2[IPT / 2], az2[IPT / 2];
    float n1[IPT], mn[IPT];
#pragma unroll
    for (int kk = 0; kk < IPT / 2; kk++) {
        int i0 = iBase + threadIdx.x + (2 * kk) * 256;
        int i1 = iBase + threadIdx.x + (2 * kk + 1) * 256;
        float x0 = Ab[i0 * 3 + 0], y0 = Ab[i0 * 3 + 1], z0 = Ab[i0 * 3 + 2];
        float x1 = Ab[i1 * 3 + 0], y1 = Ab[i1 * 3 + 1], z1 = Ab[i1 * 3 + 2];
        PACK2(ax2[kk], x0, x1);
        PACK2(ay2[kk], y0, y1);
        PACK2(az2[kk], z0, z1);
        n1[2 * kk]     = fmaf(x0, x0, fmaf(y0, y0, z0 * z0));
        n1[2 * kk + 1] = fmaf(x1, x1, fmaf(y1, y1, z1 * z1));
        mn[2 * kk] = 3.4e38f;
        mn[2 * kk + 1] = 3.4e38f;
    }

    const int jchunk = MPTS / JSPLIT;
    for (int j0 = 0; j0 < jchunk; j0 += TJ) {
        __syncthreads();
        for (int jj = threadIdx.x; jj < TJ; jj += 256) {
            int j = jBase + j0 + jj;
            float x = Bb[j * 3 + 0];
            float y = Bb[j * 3 + 1];
            float z = Bb[j * 3 + 2];
            float n2 = fmaf(x, x, fmaf(y, y, z * z));
            tile[jj] = make_float4(-2.f * x, -2.f * y, -2.f * z, n2);
        }
        __syncthreads();

#pragma unroll 2
        for (int jj = 0; jj < TJ; jj++) {
            float4 bv = tile[jj];
            unsigned long long bx2, by2, bz2, bw2;
            PACK2(bx2, bv.x, bv.x);
            PACK2(by2, bv.y, bv.y);
            PACK2(bz2, bv.z, bv.z);
            PACK2(bw2, bv.w, bv.w);
#pragma unroll
            for (int kk = 0; kk < IPT / 2; kk++) {
                unsigned long long t2;
                FMA2(t2, bx2, ax2[kk], bw2);
                FMA2(t2, by2, ay2[kk], t2);
                FMA2(t2, bz2, az2[kk], t2);
                float t0, t1;
                UNPACK2(t0, t1, t2);
                mn[2 * kk]     = fminf(mn[2 * kk], t0);
                mn[2 * kk + 1] = fminf(mn[2 * kk + 1], t1);
            }
        }
    }

#pragma unroll
    for (int k = 0; k < IPT; k++) {
        int kk = k / 2, half = k & 1;
        int i = iBase + threadIdx.x + (2 * kk + half) * 256;
        float d = fmaxf(mn[k] + n1[k], 0.f);  // clamp >= 0 keeps int-ordered atomicMin valid
        atomicMin((int*)&outmin[i], __float_as_int(d));
    }
}

// Stage A: 64 blocks; blocks 0-31 sum g_d1 stripes, 32-63 sum g_d2 stripes.
__global__ void chamfer_reduceA_kernel() {
    const float* src = (blockIdx.x < 32) ? g_d1 : g_d2;
    int base = (blockIdx.x & 31) * 1024;
    float s = 0.f;
    for (int k = threadIdx.x; k < 1024; k += 256)
        s += src[base + k] * (1.f / (BB * NPTS));
#pragma unroll
    for (int o = 16; o > 0; o >>= 1) s += __shfl_down_sync(0xffffffffu, s, o);
    __shared__ float sh[8];
    if ((threadIdx.x & 31) == 0) sh[threadIdx.x >> 5] = s;
    __syncthreads();
    if (threadIdx.x < 8) {
        float v = sh[threadIdx.x];
#pragma unroll
        for (int o = 4; o > 0; o >>= 1) v += __shfl_down_sync(0xffu, v, o);
        if (threadIdx.x == 0) g_part[blockIdx.x] = v;
    }
}

__global__ void chamfer_reduceB_kernel(float* __restrict__ out) {
    float s = (threadIdx.x < 64) ? g_part[threadIdx.x] : 0.f;
#pragma unroll
    for (int o = 16; o > 0; o >>= 1) s += __shfl_down_sync(0xffffffffu, s, o);
    __shared__ float sh[2];
    if ((threadIdx.x & 31) == 0) sh[threadIdx.x >> 5] = s;
    __syncthreads();
    if (threadIdx.x == 0) out[0] = sh[0] + sh[1];
}

extern "C" void kernel_launch(void* const* d_in, const int* in_sizes, int n_in,
                              void* d_out, int out_size) {
    const float* xyz1 = (const float*)d_in[0];
    const float* xyz2 = (const float*)d_in[1];
    float* out = (float*)d_out;

    chamfer_init_kernel<<<(BB * NPTS + 255) / 256, 256>>>();

    // Both directions in one launch: z = dir*BB + b
    dim3 grid(NPTS / (256 * IPT), JSPLIT, 2 * BB);
    chamfer_min_kernel<<<grid, 256>>>(xyz1, xyz2);

    chamfer_reduceA_kernel<<<64, 256>>>();
    chamfer_reduceB_kernel<<<1, 64>>>(out);
}

// round 4
// speedup vs baseline: 1.0466x; 1.0438x over previous
#include <cuda_runtime.h>

// ChamferLoss fused single-pass: B=4, N=M=8192, 3D.
// t = n1_i + n2_j - 2 p_i.q_j = dist^2 computed packed f32x2 (2 i-points/op):
//   w = add.rn.f32x2(n1_pack, {n2,n2}); t = fma chain over z,y,x  (4 fma-pipe ops / 2 pairs)
// row-min AND col-min both taken from the same t (scalar FMNMX on halves, alu pipe).
// B-tile pre-duplicated in smem so LDS.128 yields packed operands (no pack MOVs).

#define BB 4
#define NPTS 8192
#define MPTS 8192
#define THREADS 128
#define IPT 16
#define KKN (IPT / 2)
#define ITILES (NPTS / (THREADS * IPT))   // 4
#define JT 32
#define JCH (MPTS / JT)                   // 256

typedef unsigned long long u64;

__device__ float g_d1[BB * NPTS];
__device__ float g_d2[BB * MPTS];

#define PACK2(o, lo, hi)   asm("mov.b64 %0,{%1,%2};" : "=l"(o) : "f"(lo), "f"(hi))
#define UNPACK2(lo, hi, i) asm("mov.b64 {%0,%1},%2;" : "=f"(lo), "=f"(hi) : "l"(i))
#define FMA2(d, a, b, c)   asm("fma.rn.f32x2 %0,%1,%2,%3;" : "=l"(d) : "l"(a), "l"(b), "l"(c))
#define ADD2(d, a, b)      asm("add.rn.f32x2 %0,%1,%2;" : "=l"(d) : "l"(a), "l"(b))

__global__ void chamfer_init_kernel(float* out) {
    int idx = blockIdx.x * blockDim.x + threadIdx.x;
    if (idx < BB * NPTS) ((int*)g_d1)[idx] = 0x7f800000;
    if (idx < BB * MPTS) ((int*)g_d2)[idx] = 0x7f800000;
    if (idx == 0) out[0] = 0.f;
}

__global__ void __launch_bounds__(THREADS) chamfer_fused_kernel(
    const float* __restrict__ xyz1, const float* __restrict__ xyz2)
{
    __shared__ ulonglong2 tA[JCH];   // (-2x,-2x | -2y,-2y)
    __shared__ ulonglong2 tB[JCH];   // (-2z,-2z |  n2, n2)
    __shared__ int colmn[JCH];

    const int tid = threadIdx.x;
    const int b = blockIdx.z;
    const int iBase = blockIdx.x * (THREADS * IPT);
    const int jBase = blockIdx.y * JCH;
    const float* __restrict__ P = xyz1 + (size_t)b * NPTS * 3;
    const float* __restrict__ Q = xyz2 + (size_t)b * MPTS * 3;

    u64 ax2[KKN], ay2[KKN], az2[KKN], n12[KKN];
    float mn[IPT];
#pragma unroll
    for (int kk = 0; kk < KKN; kk++) {
        int i0 = iBase + tid + (2 * kk) * THREADS;
        int i1 = iBase + tid + (2 * kk + 1) * THREADS;
        float x0 = P[i0 * 3], y0 = P[i0 * 3 + 1], z0 = P[i0 * 3 + 2];
        float x1 = P[i1 * 3], y1 = P[i1 * 3 + 1], z1 = P[i1 * 3 + 2];
        PACK2(ax2[kk], x0, x1);
        PACK2(ay2[kk], y0, y1);
        PACK2(az2[kk], z0, z1);
        float n0 = fmaf(x0, x0, fmaf(y0, y0, z0 * z0));
        float n1 = fmaf(x1, x1, fmaf(y1, y1, z1 * z1));
        PACK2(n12[kk], n0, n1);
        mn[2 * kk] = 3.4e38f;
        mn[2 * kk + 1] = 3.4e38f;
    }

    for (int jj = tid; jj < JCH; jj += THREADS) {
        int j = jBase + jj;
        float x = Q[j * 3], y = Q[j * 3 + 1], z = Q[j * 3 + 2];
        float n2 = fmaf(x, x, fmaf(y, y, z * z));
        float nx = -2.f * x, ny = -2.f * y, nz = -2.f * z;
        u64 X2, Y2, Z2, W2;
        PACK2(X2, nx, nx);
        PACK2(Y2, ny, ny);
        PACK2(Z2, nz, nz);
        PACK2(W2, n2, n2);
        tA[jj] = make_ulonglong2(X2, Y2);
        tB[jj] = make_ulonglong2(Z2, W2);
        colmn[jj] = 0x7f800000;
    }
    __syncthreads();

    for (int jj = 0; jj < JCH; jj++) {
        ulonglong2 ba = tA[jj];   // X2, Y2
        ulonglong2 bb = tB[jj];   // Z2, W2
        float c0 = 3.4e38f, c1 = 3.4e38f;
#pragma unroll
        for (int kk = 0; kk < KKN; kk++) {
            u64 w, t;
            ADD2(w, n12[kk], bb.y);        // n1 + n2
            FMA2(t, bb.x, az2[kk], w);     // += -2z*az
            FMA2(t, ba.y, ay2[kk], t);     // += -2y*ay
            FMA2(t, ba.x, ax2[kk], t);     // += -2x*ax  -> dist^2 x2
            float t0, t1;
            UNPACK2(t0, t1, t);            // register aliasing (free in SASS)
            mn[2 * kk]     = fminf(mn[2 * kk], t0);
            mn[2 * kk + 1] = fminf(mn[2 * kk + 1], t1);
            c0 = fminf(c0, t0);
            c1 = fminf(c1, t1);
        }
        float cv = fminf(c0, c1);
#pragma unroll
        for (int o = 16; o > 0; o >>= 1)
            cv = fminf(cv, __shfl_xor_sync(0xffffffffu, cv, o));
        if ((tid & 31) == 0)
            atomicMin(&colmn[jj], __float_as_int(fmaxf(cv, 0.f)));
    }
    __syncthreads();

    for (int jj = tid; jj < JCH; jj += THREADS)
        atomicMin((int*)&g_d2[b * MPTS + jBase + jj], colmn[jj]);

#pragma unroll
    for (int kk = 0; kk < KKN; kk++) {
        int i0 = iBase + tid + (2 * kk) * THREADS;
        int i1 = iBase + tid + (2 * kk + 1) * THREADS;
        atomicMin((int*)&g_d1[b * NPTS + i0], __float_as_int(fmaxf(mn[2 * kk], 0.f)));
        atomicMin((int*)&g_d1[b * NPTS + i1], __float_as_int(fmaxf(mn[2 * kk + 1], 0.f)));
    }
}

__global__ void chamfer_reduce_kernel(float* __restrict__ out) {
    const float* src = (blockIdx.x < 32) ? g_d1 : g_d2;
    int base = (blockIdx.x & 31) * 1024;
    float s = 0.f;
    for (int k = threadIdx.x; k < 1024; k += 256)
        s += src[base + k] * (1.f / (BB * NPTS));
#pragma unroll
    for (int o = 16; o > 0; o >>= 1) s += __shfl_down_sync(0xffffffffu, s, o);
    __shared__ float sh[8];
    if ((threadIdx.x & 31) == 0) sh[threadIdx.x >> 5] = s;
    __syncthreads();
    if (threadIdx.x < 8) {
        float v = sh[threadIdx.x];
#pragma unroll
        for (int o = 4; o > 0; o >>= 1) v += __shfl_down_sync(0xffu, v, o);
        if (threadIdx.x == 0) atomicAdd(out, v);
    }
}

extern "C" void kernel_launch(void* const* d_in, const int* in_sizes, int n_in,
                              void* d_out, int out_size) {
    const float* xyz1 = (const float*)d_in[0];
    const float* xyz2 = (const float*)d_in[1];
    float* out = (float*)d_out;

    chamfer_init_kernel<<<(BB * NPTS + 255) / 256, 256>>>(out);

    dim3 grid(ITILES, JT, BB);  // 512 blocks
    chamfer_fused_kernel<<<grid, THREADS>>>(xyz1, xyz2);

    chamfer_reduce_kernel<<<64, 256>>>(out);
}

// round 5
// speedup vs baseline: 1.4255x; 1.3620x over previous
#include <cuda_runtime.h>

// ChamferLoss fused single-pass, B=4, N=M=8192, 3D.
// dist^2 = (n1_i + n2_j) - 2 p_i.q_j, packed f32x2 (2 i-points per op).
// Row-min and col-min both from one pass. Col-min shfl trees batched G=8 jjs
// (pipelined butterflies) + spread-address smem atomics.

#define BB 4
#define NPTS 8192
#define MPTS 8192
#define THREADS 128
#define IPT 16
#define KKN (IPT / 2)
#define ITILES (NPTS / (THREADS * IPT))   // 4
#define JT 64
#define JCH (MPTS / JT)                   // 128
#define G 8

typedef unsigned long long u64;

__device__ float g_d1[BB * NPTS];
__device__ float g_d2[BB * MPTS];

#define PACK2(o, lo, hi)   asm("mov.b64 %0,{%1,%2};" : "=l"(o) : "f"(lo), "f"(hi))
#define UNPACK2(lo, hi, i) asm("mov.b64 {%0,%1},%2;" : "=f"(lo), "=f"(hi) : "l"(i))
#define FMA2(d, a, b, c)   asm("fma.rn.f32x2 %0,%1,%2,%3;" : "=l"(d) : "l"(a), "l"(b), "l"(c))
#define ADD2(d, a, b)      asm("add.rn.f32x2 %0,%1,%2;" : "=l"(d) : "l"(a), "l"(b))

__global__ void chamfer_init_kernel(float* out) {
    int idx = blockIdx.x * blockDim.x + threadIdx.x;   // 16384 threads
    int4 inf4 = make_int4(0x7f800000, 0x7f800000, 0x7f800000, 0x7f800000);
    if (idx < (BB * NPTS) / 4) ((int4*)g_d1)[idx] = inf4;
    else ((int4*)g_d2)[idx - (BB * NPTS) / 4] = inf4;
    if (idx == 0) out[0] = 0.f;
}

__global__ void __launch_bounds__(THREADS) chamfer_fused_kernel(
    const float* __restrict__ xyz1, const float* __restrict__ xyz2)
{
    __shared__ ulonglong2 tA[JCH];   // (-2x,-2x | -2y,-2y)
    __shared__ ulonglong2 tB[JCH];   // (-2z,-2z |  n2, n2)
    __shared__ int colmn[JCH];

    const int tid = threadIdx.x;
    const int lane = tid & 31;
    const int b = blockIdx.z;
    const int iBase = blockIdx.x * (THREADS * IPT);
    const int jBase = blockIdx.y * JCH;
    const float* __restrict__ P = xyz1 + (size_t)b * NPTS * 3;
    const float* __restrict__ Q = xyz2 + (size_t)b * MPTS * 3;

    u64 ax2[KKN], ay2[KKN], az2[KKN], n12[KKN];
    float mn[IPT];
#pragma unroll
    for (int kk = 0; kk < KKN; kk++) {
        int i0 = iBase + tid + (2 * kk) * THREADS;
        int i1 = iBase + tid + (2 * kk + 1) * THREADS;
        float x0 = P[i0 * 3], y0 = P[i0 * 3 + 1], z0 = P[i0 * 3 + 2];
        float x1 = P[i1 * 3], y1 = P[i1 * 3 + 1], z1 = P[i1 * 3 + 2];
        PACK2(ax2[kk], x0, x1);
        PACK2(ay2[kk], y0, y1);
        PACK2(az2[kk], z0, z1);
        float n0 = fmaf(x0, x0, fmaf(y0, y0, z0 * z0));
        float n1 = fmaf(x1, x1, fmaf(y1, y1, z1 * z1));
        PACK2(n12[kk], n0, n1);
        mn[2 * kk] = 3.4e38f;
        mn[2 * kk + 1] = 3.4e38f;
    }

    for (int jj = tid; jj < JCH; jj += THREADS) {
        int j = jBase + jj;
        float x = Q[j * 3], y = Q[j * 3 + 1], z = Q[j * 3 + 2];
        float n2 = fmaf(x, x, fmaf(y, y, z * z));
        float nx = -2.f * x, ny = -2.f * y, nz = -2.f * z;
        u64 X2, Y2, Z2, W2;
        PACK2(X2, nx, nx);
        PACK2(Y2, ny, ny);
        PACK2(Z2, nz, nz);
        PACK2(W2, n2, n2);
        tA[jj] = make_ulonglong2(X2, Y2);
        tB[jj] = make_ulonglong2(Z2, W2);
        colmn[jj] = 0x7f800000;
    }
    __syncthreads();

    for (int jj0 = 0; jj0 < JCH; jj0 += G) {
        float cv[G];
#pragma unroll
        for (int g = 0; g < G; g++) {
            ulonglong2 ba = tA[jj0 + g];   // X2, Y2
            ulonglong2 bb = tB[jj0 + g];   // Z2, W2
            float c0 = 3.4e38f, c1 = 3.4e38f;
#pragma unroll
            for (int kk = 0; kk < KKN; kk++) {
                u64 w, t;
                ADD2(w, n12[kk], bb.y);
                FMA2(t, bb.x, az2[kk], w);
                FMA2(t, ba.y, ay2[kk], t);
                FMA2(t, ba.x, ax2[kk], t);
                float t0, t1;
                UNPACK2(t0, t1, t);
                mn[2 * kk]     = fminf(mn[2 * kk], t0);
                mn[2 * kk + 1] = fminf(mn[2 * kk + 1], t1);
                c0 = fminf(c0, t0);
                c1 = fminf(c1, t1);
            }
            cv[g] = fminf(c0, c1);
        }
        // 8 independent butterfly chains, pipelined.
#pragma unroll
        for (int o = 16; o > 0; o >>= 1)
#pragma unroll
            for (int g = 0; g < G; g++)
                cv[g] = fminf(cv[g], __shfl_xor_sync(0xffffffffu, cv[g], o));
        // lane g writes result g (spread-address smem atomics)
        float myv = cv[0];
#pragma unroll
        for (int g = 1; g < G; g++)
            if (lane == g) myv = cv[g];
        if (lane < G)
            atomicMin(&colmn[jj0 + lane], __float_as_int(fmaxf(myv, 0.f)));
    }
    __syncthreads();

    for (int jj = tid; jj < JCH; jj += THREADS)
        atomicMin((int*)&g_d2[b * MPTS + jBase + jj], colmn[jj]);

#pragma unroll
    for (int kk = 0; kk < KKN; kk++) {
        int i0 = iBase + tid + (2 * kk) * THREADS;
        int i1 = iBase + tid + (2 * kk + 1) * THREADS;
        atomicMin((int*)&g_d1[b * NPTS + i0], __float_as_int(fmaxf(mn[2 * kk], 0.f)));
        atomicMin((int*)&g_d1[b * NPTS + i1], __float_as_int(fmaxf(mn[2 * kk + 1], 0.f)));
    }
}

__global__ void chamfer_reduce_kernel(float* __restrict__ out) {
    const float* src = (blockIdx.x < 32) ? g_d1 : g_d2;
    int base = (blockIdx.x & 31) * 1024;
    float s = 0.f;
    for (int k = threadIdx.x; k < 1024; k += 256)
        s += src[base + k] * (1.f / (BB * NPTS));
#pragma unroll
    for (int o = 16; o > 0; o >>= 1) s += __shfl_down_sync(0xffffffffu, s, o);
    __shared__ float sh[8];
    if ((threadIdx.x & 31) == 0) sh[threadIdx.x >> 5] = s;
    __syncthreads();
    if (threadIdx.x < 8) {
        float v = sh[threadIdx.x];
#pragma unroll
        for (int o = 4; o > 0; o >>= 1) v += __shfl_down_sync(0xffu, v, o);
        if (threadIdx.x == 0) atomicAdd(out, v);
    }
}

extern "C" void kernel_launch(void* const* d_in, const int* in_sizes, int n_in,
                              void* d_out, int out_size) {
    const float* xyz1 = (const float*)d_in[0];
    const float* xyz2 = (const float*)d_in[1];
    float* out = (float*)d_out;

    chamfer_init_kernel<<<64, 256>>>(out);

    dim3 grid(ITILES, JT, BB);  // (4, 64, 4) = 1024 blocks
    chamfer_fused_kernel<<<grid, THREADS>>>(xyz1, xyz2);

    chamfer_reduce_kernel<<<64, 256>>>(out);
}